// round 4
// baseline (speedup 1.0000x reference)
#include <cuda_runtime.h>

#define NN 100000
#define EE 1600000
#define GG 64
#define HID 64
#define EDIM 16
#define OUTD 128

// ---------------- scratch (device globals; no allocation) ----------------
__device__ float d_cnt[NN];
__device__ float d_loop[NN * EDIM];
__device__ float d_xl[NN * HID];
__device__ float d_xr[NN * HID];
__device__ float d_acc[NN * HID];
__device__ float d_den[NN * 4];
__device__ float d_x[NN * HID];
__device__ float d_g[GG * HID];
__device__ float d_gc[GG];

__device__ __forceinline__ void red4(float* p, float a, float b, float c, float d) {
    asm volatile("red.global.add.v4.f32 [%0], {%1,%2,%3,%4};"
                 :: "l"(p), "f"(a), "f"(b), "f"(c), "f"(d) : "memory");
}
__device__ __forceinline__ void red2(float* p, float a, float b) {
    asm volatile("red.global.add.v2.f32 [%0], {%1,%2};"
                 :: "l"(p), "f"(a), "f"(b) : "memory");
}

// ---------------- self-loop mean edge attr ----------------
__global__ void loop_accum_k(const int* __restrict__ ei, const float* __restrict__ ea) {
    int e = blockIdx.x * blockDim.x + threadIdx.x;
    if (e >= EE) return;
    int dst = ei[EE + e];
    const float4* a4 = reinterpret_cast<const float4*>(ea + (size_t)e * EDIM);
    float* o = d_loop + (size_t)dst * EDIM;
#pragma unroll
    for (int i = 0; i < 4; i++) {
        float4 v = a4[i];
        red4(o + 4 * i, v.x, v.y, v.z, v.w);
    }
    atomicAdd(&d_cnt[dst], 1.0f);
}

__global__ void loop_norm_k() {
    int t = blockIdx.x * blockDim.x + threadIdx.x;
    if (t >= NN * EDIM) return;
    float c = d_cnt[t >> 4];
    d_loop[t] = d_loop[t] / fmaxf(c, 1.0f);
}

// ---------------- node projections ----------------
__global__ void node_proj_k(const float* __restrict__ x,
                            const float* __restrict__ Wl, const float* __restrict__ bl,
                            const float* __restrict__ Wr, const float* __restrict__ br) {
    __shared__ float sWl[64 * 64];
    __shared__ float sWr[64 * 64];
    __shared__ float sx[16 * 64];
    for (int i = threadIdx.x; i < 64 * 64; i += blockDim.x) {
        sWl[i] = Wl[i];
        sWr[i] = Wr[i];
    }
    int c  = threadIdx.x & 63;
    int rl = threadIdx.x >> 6;
    float blc = bl[c], brc = br[c];
    for (int base = blockIdx.x * 16; base < NN; base += gridDim.x * 16) {
        __syncthreads();
        for (int i = threadIdx.x; i < 16 * 64; i += 256) {
            int r = base + (i >> 6);
            sx[i] = (r < NN) ? x[(size_t)r * 64 + (i & 63)] : 0.0f;
        }
        __syncthreads();
        float s0 = blc, s1 = blc, s2 = blc, s3 = blc;
        float t0 = brc, t1 = brc, t2 = brc, t3 = brc;
        const float* xrow = sx + rl * 4 * 64;
#pragma unroll
        for (int k = 0; k < 64; k++) {
            float wl = sWl[k * 64 + c];
            float wr = sWr[k * 64 + c];
            float x0 = xrow[0 * 64 + k];
            float x1 = xrow[1 * 64 + k];
            float x2 = xrow[2 * 64 + k];
            float x3 = xrow[3 * 64 + k];
            s0 += x0 * wl; t0 += x0 * wr;
            s1 += x1 * wl; t1 += x1 * wr;
            s2 += x2 * wl; t2 += x2 * wr;
            s3 += x3 * wl; t3 += x3 * wr;
        }
        int r0 = base + rl * 4;
        if (r0 + 0 < NN) { d_xl[(size_t)(r0 + 0) * 64 + c] = s0; d_xr[(size_t)(r0 + 0) * 64 + c] = t0; }
        if (r0 + 1 < NN) { d_xl[(size_t)(r0 + 1) * 64 + c] = s1; d_xr[(size_t)(r0 + 1) * 64 + c] = t1; }
        if (r0 + 2 < NN) { d_xl[(size_t)(r0 + 2) * 64 + c] = s2; d_xr[(size_t)(r0 + 2) * 64 + c] = t2; }
        if (r0 + 3 < NN) { d_xl[(size_t)(r0 + 3) * 64 + c] = s3; d_xr[(size_t)(r0 + 3) * 64 + c] = t3; }
    }
}

// ---------------- fused edge pass: 2 edges per warp iteration ----------------
// Edge pair (2i, 2i+1). Lane l owns channels {2l,2l+1}; head = lane>>3.
// ea: one coalesced LDG.32 per lane covers BOTH edges' 16 attrs (128B aligned).
// All loads issued up front -> 2 edges of memory in flight per warp.
__global__ __launch_bounds__(128, 6)
void edge_pass_k(const int* __restrict__ ei, const float* __restrict__ ea,
                 const float* __restrict__ We, const float* __restrict__ att) {
    const unsigned F = 0xffffffffu;
    int lane = threadIdx.x & 31;

    float2 w[EDIM];
    const float2* We2 = reinterpret_cast<const float2*>(We);
#pragma unroll
    for (int k = 0; k < EDIM; k++) w[k] = We2[k * 32 + lane];
    float2 at = reinterpret_cast<const float2*>(att)[lane];

    int wid = (blockIdx.x * blockDim.x + threadIdx.x) >> 5;
    int nwarp = (gridDim.x * blockDim.x) >> 5;
    const float2* xl2p = reinterpret_cast<const float2*>(d_xl);
    const float2* xr2p = reinterpret_cast<const float2*>(d_xr);

    for (int i = wid; i < EE / 2; i += nwarp) {
        int e0 = 2 * i;
        int2 sp = *reinterpret_cast<const int2*>(ei + e0);        // src0, src1
        int2 dp = *reinterpret_cast<const int2*>(ei + EE + e0);   // dst0, dst1
        float av = ea[(size_t)e0 * EDIM + lane];                  // both edges' attrs
        float2 xl0 = xl2p[(size_t)sp.x * 32 + lane];
        float2 xr0 = xr2p[(size_t)dp.x * 32 + lane];
        float2 xl1 = xl2p[(size_t)sp.y * 32 + lane];
        float2 xr1 = xr2p[(size_t)dp.y * 32 + lane];

        float ex0 = 0.0f, ey0 = 0.0f, ex1 = 0.0f, ey1 = 0.0f;
#pragma unroll
        for (int k = 0; k < EDIM; k++) {
            float a0 = __shfl_sync(F, av, k);
            float a1 = __shfl_sync(F, av, k + 16);
            ex0 += a0 * w[k].x;
            ey0 += a0 * w[k].y;
            ex1 += a1 * w[k].x;
            ey1 += a1 * w[k].y;
        }
        float m00 = xl0.x + xr0.x + ex0;
        float m01 = xl0.y + xr0.y + ey0;
        float m10 = xl1.x + xr1.x + ex1;
        float m11 = xl1.y + xr1.y + ey1;
        m00 = (m00 > 0.0f) ? m00 : 0.2f * m00;
        m01 = (m01 > 0.0f) ? m01 : 0.2f * m01;
        m10 = (m10 > 0.0f) ? m10 : 0.2f * m10;
        m11 = (m11 > 0.0f) ? m11 : 0.2f * m11;
        float s0 = m00 * at.x + m01 * at.y;
        float s1 = m10 * at.x + m11 * at.y;
        s0 += __shfl_xor_sync(F, s0, 1);
        s1 += __shfl_xor_sync(F, s1, 1);
        s0 += __shfl_xor_sync(F, s0, 2);
        s1 += __shfl_xor_sync(F, s1, 2);
        s0 += __shfl_xor_sync(F, s0, 4);
        s1 += __shfl_xor_sync(F, s1, 4);
        float z0 = __expf(s0);
        float z1 = __expf(s1);

        red2(d_acc + (size_t)dp.x * 64 + 2 * lane, z0 * xl0.x, z0 * xl0.y);
        red2(d_acc + (size_t)dp.y * 64 + 2 * lane, z1 * xl1.x, z1 * xl1.y);
        if ((lane & 7) == 0) {
            atomicAdd(&d_den[(size_t)dp.x * 4 + (lane >> 3)], z0);
            atomicAdd(&d_den[(size_t)dp.y * 4 + (lane >> 3)], z1);
        }
    }
}

// ---------------- self-loop edges (src=dst=n, attr=d_loop[n]) ----------------
__global__ void self_loop_k(const float* __restrict__ We, const float* __restrict__ att) {
    const unsigned F = 0xffffffffu;
    int lane = threadIdx.x & 31;
    float2 w[EDIM];
    const float2* We2 = reinterpret_cast<const float2*>(We);
#pragma unroll
    for (int k = 0; k < EDIM; k++) w[k] = We2[k * 32 + lane];
    float2 at = reinterpret_cast<const float2*>(att)[lane];

    int wid = (blockIdx.x * blockDim.x + threadIdx.x) >> 5;
    int nwarp = (gridDim.x * blockDim.x) >> 5;
    const float2* xl2p = reinterpret_cast<const float2*>(d_xl);
    const float2* xr2p = reinterpret_cast<const float2*>(d_xr);

    for (int n = wid; n < NN; n += nwarp) {
        float av = (lane < EDIM) ? d_loop[(size_t)n * EDIM + lane] : 0.0f;
        float2 xl2 = xl2p[(size_t)n * 32 + lane];
        float2 xr2 = xr2p[(size_t)n * 32 + lane];
        float epx = 0.0f, epy = 0.0f;
#pragma unroll
        for (int k = 0; k < EDIM; k++) {
            float a = __shfl_sync(F, av, k);
            epx += a * w[k].x;
            epy += a * w[k].y;
        }
        float m0 = xl2.x + xr2.x + epx;
        float m1 = xl2.y + xr2.y + epy;
        m0 = (m0 > 0.0f) ? m0 : 0.2f * m0;
        m1 = (m1 > 0.0f) ? m1 : 0.2f * m1;
        float s = m0 * at.x + m1 * at.y;
        s += __shfl_xor_sync(F, s, 1);
        s += __shfl_xor_sync(F, s, 2);
        s += __shfl_xor_sync(F, s, 4);
        float z = __expf(s);
        red2(d_acc + (size_t)n * 64 + 2 * lane, z * xl2.x, z * xl2.y);
        if ((lane & 7) == 0)
            atomicAdd(&d_den[(size_t)n * 4 + (lane >> 3)], z);
    }
}

// ---------------- finalize layer 0: d_x = relu(acc/den + bias), float4 ----------------
__global__ void node_out_k(const float* __restrict__ bias) {
    int t = blockIdx.x * blockDim.x + threadIdx.x;
    if (t >= NN * 16) return;
    int node = t >> 4;
    int part = t & 15;
    float inv = 1.0f / d_den[node * 4 + (part >> 2)];
    float4 a = reinterpret_cast<const float4*>(d_acc)[t];
    float4 b = reinterpret_cast<const float4*>(bias)[part];
    float4 v;
    v.x = fmaxf(a.x * inv + b.x, 0.0f);
    v.y = fmaxf(a.y * inv + b.y, 0.0f);
    v.z = fmaxf(a.z * inv + b.z, 0.0f);
    v.w = fmaxf(a.w * inv + b.w, 0.0f);
    reinterpret_cast<float4*>(d_x)[t] = v;
}

// ---------------- finalize layer 1 fused with global mean pool ----------------
__global__ void node_out_pool_k(const float* __restrict__ bias, const int* __restrict__ batch) {
    int t = blockIdx.x * blockDim.x + threadIdx.x;
    if (t >= NN * 16) return;
    int node = t >> 4;
    int part = t & 15;
    float inv = 1.0f / d_den[node * 4 + (part >> 2)];
    float4 a = reinterpret_cast<const float4*>(d_acc)[t];
    float4 b = reinterpret_cast<const float4*>(bias)[part];
    float vx = fmaxf(a.x * inv + b.x, 0.0f);
    float vy = fmaxf(a.y * inv + b.y, 0.0f);
    float vz = fmaxf(a.z * inv + b.z, 0.0f);
    float vw = fmaxf(a.w * inv + b.w, 0.0f);
    int g = batch[node];
    red4(d_g + g * 64 + part * 4, vx, vy, vz, vw);
    if (part == 0) atomicAdd(&d_gc[g], 1.0f);
}

// ---------------- MLP head ----------------
__global__ void mlp_k(const float* __restrict__ W1, const float* __restrict__ b1,
                      const float* __restrict__ W2, const float* __restrict__ b2,
                      float* __restrict__ out) {
    __shared__ float gx[64];
    __shared__ float hh[128];
    int g = blockIdx.x;
    int t = threadIdx.x;
    if (t < 64) gx[t] = d_g[g * 64 + t] / fmaxf(d_gc[g], 1.0f);
    __syncthreads();
    float s = b1[t];
#pragma unroll
    for (int k = 0; k < 64; k++) s += gx[k] * W1[k * 128 + t];
    hh[t] = fmaxf(s, 0.0f);
    __syncthreads();
    float o = b2[t];
#pragma unroll
    for (int k = 0; k < 128; k++) o += hh[k] * W2[k * 128 + t];
    out[g * 128 + t] = o;
}

// ---------------- launch ----------------
extern "C" void kernel_launch(void* const* d_in, const int* in_sizes, int n_in,
                              void* d_out, int out_size) {
    const float* x0     = (const float*)d_in[0];
    const int*   ei     = (const int*)d_in[1];
    const float* ea     = (const float*)d_in[2];
    const int*   batch  = (const int*)d_in[3];
    const float* l0Wl   = (const float*)d_in[4];
    const float* l0bl   = (const float*)d_in[5];
    const float* l0Wr   = (const float*)d_in[6];
    const float* l0br   = (const float*)d_in[7];
    const float* l0We   = (const float*)d_in[8];
    const float* l0att  = (const float*)d_in[9];
    const float* l0bias = (const float*)d_in[10];
    const float* l1Wl   = (const float*)d_in[11];
    const float* l1bl   = (const float*)d_in[12];
    const float* l1Wr   = (const float*)d_in[13];
    const float* l1br   = (const float*)d_in[14];
    const float* l1We   = (const float*)d_in[15];
    const float* l1att  = (const float*)d_in[16];
    const float* l1bias = (const float*)d_in[17];
    const float* W1     = (const float*)d_in[18];
    const float* b1     = (const float*)d_in[19];
    const float* W2     = (const float*)d_in[20];
    const float* b2     = (const float*)d_in[21];
    float* out = (float*)d_out;

    void *pcnt, *ploop, *pacc, *pden, *pg, *pgc, *px;
    cudaGetSymbolAddress(&pcnt, d_cnt);
    cudaGetSymbolAddress(&ploop, d_loop);
    cudaGetSymbolAddress(&pacc, d_acc);
    cudaGetSymbolAddress(&pden, d_den);
    cudaGetSymbolAddress(&pg, d_g);
    cudaGetSymbolAddress(&pgc, d_gc);
    cudaGetSymbolAddress(&px, d_x);

    cudaMemsetAsync(pcnt, 0, NN * sizeof(float));
    cudaMemsetAsync(ploop, 0, NN * EDIM * sizeof(float));
    cudaMemsetAsync(pg, 0, GG * HID * sizeof(float));
    cudaMemsetAsync(pgc, 0, GG * sizeof(float));

    loop_accum_k<<<(EE + 255) / 256, 256>>>(ei, ea);
    loop_norm_k<<<(NN * EDIM + 255) / 256, 256>>>();

    // ---- layer 0 ----
    node_proj_k<<<2048, 256>>>(x0, l0Wl, l0bl, l0Wr, l0br);
    cudaMemsetAsync(pacc, 0, (size_t)NN * HID * sizeof(float));
    cudaMemsetAsync(pden, 0, (size_t)NN * 4 * sizeof(float));
    edge_pass_k<<<1776, 128>>>(ei, ea, l0We, l0att);
    self_loop_k<<<888, 128>>>(l0We, l0att);
    node_out_k<<<(NN * 16 + 255) / 256, 256>>>(l0bias);

    // ---- layer 1 ----
    node_proj_k<<<2048, 256>>>((const float*)px, l1Wl, l1bl, l1Wr, l1br);
    cudaMemsetAsync(pacc, 0, (size_t)NN * HID * sizeof(float));
    cudaMemsetAsync(pden, 0, (size_t)NN * 4 * sizeof(float));
    edge_pass_k<<<1776, 128>>>(ei, ea, l1We, l1att);
    self_loop_k<<<888, 128>>>(l1We, l1att);
    node_out_pool_k<<<(NN * 16 + 255) / 256, 256>>>(l1bias, batch);

    // ---- MLP ----
    mlp_k<<<GG, OUTD>>>(W1, b1, W2, b2, out);
}

// round 6
// speedup vs baseline: 1.2719x; 1.2719x over previous
#include <cuda_runtime.h>

#define NN 100000
#define EE 1600000
#define E2 (EE + NN)
#define GG 64
#define HID 64
#define EDIM 16
#define OUTD 128

// ---------------- scratch (device globals; no allocation) ----------------
__device__ float d_cnt[NN];
__device__ float d_loop[NN * EDIM];
__device__ float d_xl[NN * HID];
__device__ float d_xr[NN * HID];
__device__ float d_acc[NN * HID];
__device__ float d_den[NN * 4];
__device__ float d_x[NN * HID];
__device__ float d_g[GG * HID];
__device__ float d_gc[GG];
__device__ float d_ep[(size_t)E2 * HID];   // precomputed ea @ We (435 MB)

__device__ __forceinline__ void red4(float* p, float a, float b, float c, float d) {
    asm volatile("red.global.add.v4.f32 [%0], {%1,%2,%3,%4};"
                 :: "l"(p), "f"(a), "f"(b), "f"(c), "f"(d) : "memory");
}
__device__ __forceinline__ void red2(float* p, float a, float b) {
    asm volatile("red.global.add.v2.f32 [%0], {%1,%2};"
                 :: "l"(p), "f"(a), "f"(b) : "memory");
}

// ---------------- self-loop mean edge attr ----------------
__global__ void loop_accum_k(const int* __restrict__ ei, const float* __restrict__ ea) {
    int e = blockIdx.x * blockDim.x + threadIdx.x;
    if (e >= EE) return;
    int dst = ei[EE + e];
    const float4* a4 = reinterpret_cast<const float4*>(ea + (size_t)e * EDIM);
    float* o = d_loop + (size_t)dst * EDIM;
#pragma unroll
    for (int i = 0; i < 4; i++) {
        float4 v = a4[i];
        red4(o + 4 * i, v.x, v.y, v.z, v.w);
    }
    atomicAdd(&d_cnt[dst], 1.0f);
}

__global__ void loop_norm_k() {
    int t = blockIdx.x * blockDim.x + threadIdx.x;
    if (t >= NN * EDIM) return;
    float c = d_cnt[t >> 4];
    d_loop[t] = d_loop[t] / fmaxf(c, 1.0f);
}

// ---------------- edge projection precompute: d_ep = ea @ We ----------------
// Warp handles an edge pair (attrs of both edges = one coalesced LDG.32/lane).
// Lane l owns channels {2l, 2l+1}. Streaming, compute-bound.
__global__ void ep_k(const float* __restrict__ ea, const float* __restrict__ We) {
    const unsigned F = 0xffffffffu;
    int lane = threadIdx.x & 31;
    float2 w[EDIM];
    const float2* We2 = reinterpret_cast<const float2*>(We);
#pragma unroll
    for (int k = 0; k < EDIM; k++) w[k] = We2[k * 32 + lane];

    int wid = (blockIdx.x * blockDim.x + threadIdx.x) >> 5;
    int nwarp = (gridDim.x * blockDim.x) >> 5;
    float2* ep2 = reinterpret_cast<float2*>(d_ep);

    for (int i = wid; i < E2 / 2; i += nwarp) {
        int e0 = 2 * i;
        const float* ap = (e0 < EE) ? (ea + (size_t)e0 * EDIM)
                                    : (d_loop + (size_t)(e0 - EE) * EDIM);
        float av = ap[lane];   // lanes 0-15: edge e0, lanes 16-31: edge e0+1
        float ex0 = 0.0f, ey0 = 0.0f, ex1 = 0.0f, ey1 = 0.0f;
#pragma unroll
        for (int k = 0; k < EDIM; k++) {
            float a0 = __shfl_sync(F, av, k);
            float a1 = __shfl_sync(F, av, k + 16);
            ex0 += a0 * w[k].x;
            ey0 += a0 * w[k].y;
            ex1 += a1 * w[k].x;
            ey1 += a1 * w[k].y;
        }
        ep2[(size_t)e0 * 32 + lane] = make_float2(ex0, ey0);
        ep2[(size_t)(e0 + 1) * 32 + lane] = make_float2(ex1, ey1);
    }
}

// ---------------- node projections ----------------
__global__ void node_proj_k(const float* __restrict__ x,
                            const float* __restrict__ Wl, const float* __restrict__ bl,
                            const float* __restrict__ Wr, const float* __restrict__ br) {
    __shared__ float sWl[64 * 64];
    __shared__ float sWr[64 * 64];
    __shared__ float sx[16 * 64];
    for (int i = threadIdx.x; i < 64 * 16; i += blockDim.x) {
        reinterpret_cast<float4*>(sWl)[i] = reinterpret_cast<const float4*>(Wl)[i];
        reinterpret_cast<float4*>(sWr)[i] = reinterpret_cast<const float4*>(Wr)[i];
    }
    int c  = threadIdx.x & 63;
    int rl = threadIdx.x >> 6;
    float blc = bl[c], brc = br[c];
    for (int base = blockIdx.x * 16; base < NN; base += gridDim.x * 16) {
        __syncthreads();
        for (int i = threadIdx.x; i < 16 * 16; i += 256) {
            int r = base + (i >> 4);
            reinterpret_cast<float4*>(sx)[i] = (r < NN)
                ? reinterpret_cast<const float4*>(x)[(size_t)r * 16 + (i & 15)]
                : make_float4(0.f, 0.f, 0.f, 0.f);
        }
        __syncthreads();
        float s0 = blc, s1 = blc, s2 = blc, s3 = blc;
        float t0 = brc, t1 = brc, t2 = brc, t3 = brc;
        const float* xrow = sx + rl * 4 * 64;
#pragma unroll
        for (int k = 0; k < 64; k++) {
            float wl = sWl[k * 64 + c];
            float wr = sWr[k * 64 + c];
            float x0 = xrow[0 * 64 + k];
            float x1 = xrow[1 * 64 + k];
            float x2 = xrow[2 * 64 + k];
            float x3 = xrow[3 * 64 + k];
            s0 += x0 * wl; t0 += x0 * wr;
            s1 += x1 * wl; t1 += x1 * wr;
            s2 += x2 * wl; t2 += x2 * wr;
            s3 += x3 * wl; t3 += x3 * wr;
        }
        int r0 = base + rl * 4;
        if (r0 + 0 < NN) { d_xl[(size_t)(r0 + 0) * 64 + c] = s0; d_xr[(size_t)(r0 + 0) * 64 + c] = t0; }
        if (r0 + 1 < NN) { d_xl[(size_t)(r0 + 1) * 64 + c] = s1; d_xr[(size_t)(r0 + 1) * 64 + c] = t1; }
        if (r0 + 2 < NN) { d_xl[(size_t)(r0 + 2) * 64 + c] = s2; d_xr[(size_t)(r0 + 2) * 64 + c] = t2; }
        if (r0 + 3 < NN) { d_xl[(size_t)(r0 + 3) * 64 + c] = s3; d_xr[(size_t)(r0 + 3) * 64 + c] = t3; }
    }
}

// ---------------- edge pass: gather + score + exp + atomic accumulate ----------------
// ep already materialized -> no weight registers, no eproj shuffles.
// Warp handles edge pair (2i, 2i+1); lane l owns channels {2l, 2l+1}.
// Pairs never straddle EE (both EE and NN are even).
__global__ __launch_bounds__(256)
void edge_pass_k(const int* __restrict__ ei, const float* __restrict__ att) {
    const unsigned F = 0xffffffffu;
    int lane = threadIdx.x & 31;
    float2 at = reinterpret_cast<const float2*>(att)[lane];

    int wid = (blockIdx.x * blockDim.x + threadIdx.x) >> 5;
    int nwarp = (gridDim.x * blockDim.x) >> 5;
    const float2* xl2p = reinterpret_cast<const float2*>(d_xl);
    const float2* xr2p = reinterpret_cast<const float2*>(d_xr);
    const float2* ep2 = reinterpret_cast<const float2*>(d_ep);

    for (int i = wid; i < E2 / 2; i += nwarp) {
        int e0 = 2 * i;
        int s0i, s1i, d0i, d1i;
        if (e0 < EE) {
            int2 sp = *reinterpret_cast<const int2*>(ei + e0);
            int2 dp = *reinterpret_cast<const int2*>(ei + EE + e0);
            s0i = sp.x; s1i = sp.y; d0i = dp.x; d1i = dp.y;
        } else {
            s0i = d0i = e0 - EE;
            s1i = d1i = e0 - EE + 1;
        }
        float2 ep0 = ep2[(size_t)e0 * 32 + lane];
        float2 ep1 = ep2[(size_t)(e0 + 1) * 32 + lane];
        float2 xl0 = xl2p[(size_t)s0i * 32 + lane];
        float2 xr0 = xr2p[(size_t)d0i * 32 + lane];
        float2 xl1 = xl2p[(size_t)s1i * 32 + lane];
        float2 xr1 = xr2p[(size_t)d1i * 32 + lane];

        float m00 = xl0.x + xr0.x + ep0.x;
        float m01 = xl0.y + xr0.y + ep0.y;
        float m10 = xl1.x + xr1.x + ep1.x;
        float m11 = xl1.y + xr1.y + ep1.y;
        m00 = (m00 > 0.0f) ? m00 : 0.2f * m00;
        m01 = (m01 > 0.0f) ? m01 : 0.2f * m01;
        m10 = (m10 > 0.0f) ? m10 : 0.2f * m10;
        m11 = (m11 > 0.0f) ? m11 : 0.2f * m11;
        float sc0 = m00 * at.x + m01 * at.y;
        float sc1 = m10 * at.x + m11 * at.y;
        sc0 += __shfl_xor_sync(F, sc0, 1);
        sc1 += __shfl_xor_sync(F, sc1, 1);
        sc0 += __shfl_xor_sync(F, sc0, 2);
        sc1 += __shfl_xor_sync(F, sc1, 2);
        sc0 += __shfl_xor_sync(F, sc0, 4);
        sc1 += __shfl_xor_sync(F, sc1, 4);
        float z0 = __expf(sc0);   // softmax without max-shift (scores O(1))
        float z1 = __expf(sc1);

        red2(d_acc + (size_t)d0i * 64 + 2 * lane, z0 * xl0.x, z0 * xl0.y);
        red2(d_acc + (size_t)d1i * 64 + 2 * lane, z1 * xl1.x, z1 * xl1.y);
        if ((lane & 7) == 0) {
            atomicAdd(&d_den[(size_t)d0i * 4 + (lane >> 3)], z0);
            atomicAdd(&d_den[(size_t)d1i * 4 + (lane >> 3)], z1);
        }
    }
}

// ---------------- finalize layer 0: d_x = relu(acc/den + bias) ----------------
__global__ void node_out_k(const float* __restrict__ bias) {
    int t = blockIdx.x * blockDim.x + threadIdx.x;
    if (t >= NN * 16) return;
    int node = t >> 4;
    int part = t & 15;
    float inv = 1.0f / d_den[node * 4 + (part >> 2)];
    float4 a = reinterpret_cast<const float4*>(d_acc)[t];
    float4 b = reinterpret_cast<const float4*>(bias)[part];
    float4 v;
    v.x = fmaxf(a.x * inv + b.x, 0.0f);
    v.y = fmaxf(a.y * inv + b.y, 0.0f);
    v.z = fmaxf(a.z * inv + b.z, 0.0f);
    v.w = fmaxf(a.w * inv + b.w, 0.0f);
    reinterpret_cast<float4*>(d_x)[t] = v;
}

// ---------------- finalize layer 1 fused with global mean pool ----------------
__global__ void node_out_pool_k(const float* __restrict__ bias, const int* __restrict__ batch) {
    int t = blockIdx.x * blockDim.x + threadIdx.x;
    if (t >= NN * 16) return;
    int node = t >> 4;
    int part = t & 15;
    float inv = 1.0f / d_den[node * 4 + (part >> 2)];
    float4 a = reinterpret_cast<const float4*>(d_acc)[t];
    float4 b = reinterpret_cast<const float4*>(bias)[part];
    float vx = fmaxf(a.x * inv + b.x, 0.0f);
    float vy = fmaxf(a.y * inv + b.y, 0.0f);
    float vz = fmaxf(a.z * inv + b.z, 0.0f);
    float vw = fmaxf(a.w * inv + b.w, 0.0f);
    int g = batch[node];
    red4(d_g + g * 64 + part * 4, vx, vy, vz, vw);
    if (part == 0) atomicAdd(&d_gc[g], 1.0f);
}

// ---------------- MLP head ----------------
__global__ void mlp_k(const float* __restrict__ W1, const float* __restrict__ b1,
                      const float* __restrict__ W2, const float* __restrict__ b2,
                      float* __restrict__ out) {
    __shared__ float gx[64];
    __shared__ float hh[128];
    int g = blockIdx.x;
    int t = threadIdx.x;
    if (t < 64) gx[t] = d_g[g * 64 + t] / fmaxf(d_gc[g], 1.0f);
    __syncthreads();
    float s = b1[t];
#pragma unroll
    for (int k = 0; k < 64; k++) s += gx[k] * W1[k * 128 + t];
    hh[t] = fmaxf(s, 0.0f);
    __syncthreads();
    float o = b2[t];
#pragma unroll
    for (int k = 0; k < 128; k++) o += hh[k] * W2[k * 128 + t];
    out[g * 128 + t] = o;
}

// ---------------- launch ----------------
extern "C" void kernel_launch(void* const* d_in, const int* in_sizes, int n_in,
                              void* d_out, int out_size) {
    const float* x0     = (const float*)d_in[0];
    const int*   ei     = (const int*)d_in[1];
    const float* ea     = (const float*)d_in[2];
    const int*   batch  = (const int*)d_in[3];
    const float* l0Wl   = (const float*)d_in[4];
    const float* l0bl   = (const float*)d_in[5];
    const float* l0Wr   = (const float*)d_in[6];
    const float* l0br   = (const float*)d_in[7];
    const float* l0We   = (const float*)d_in[8];
    const float* l0att  = (const float*)d_in[9];
    const float* l0bias = (const float*)d_in[10];
    const float* l1Wl   = (const float*)d_in[11];
    const float* l1bl   = (const float*)d_in[12];
    const float* l1Wr   = (const float*)d_in[13];
    const float* l1br   = (const float*)d_in[14];
    const float* l1We   = (const float*)d_in[15];
    const float* l1att  = (const float*)d_in[16];
    const float* l1bias = (const float*)d_in[17];
    const float* W1     = (const float*)d_in[18];
    const float* b1     = (const float*)d_in[19];
    const float* W2     = (const float*)d_in[20];
    const float* b2     = (const float*)d_in[21];
    float* out = (float*)d_out;

    void *pcnt, *ploop, *pacc, *pden, *pg, *pgc, *px;
    cudaGetSymbolAddress(&pcnt, d_cnt);
    cudaGetSymbolAddress(&ploop, d_loop);
    cudaGetSymbolAddress(&pacc, d_acc);
    cudaGetSymbolAddress(&pden, d_den);
    cudaGetSymbolAddress(&pg, d_g);
    cudaGetSymbolAddress(&pgc, d_gc);
    cudaGetSymbolAddress(&px, d_x);

    cudaMemsetAsync(pcnt, 0, NN * sizeof(float));
    cudaMemsetAsync(ploop, 0, NN * EDIM * sizeof(float));
    cudaMemsetAsync(pg, 0, GG * HID * sizeof(float));
    cudaMemsetAsync(pgc, 0, GG * sizeof(float));

    loop_accum_k<<<(EE + 255) / 256, 256>>>(ei, ea);
    loop_norm_k<<<(NN * EDIM + 255) / 256, 256>>>();

    // ---- layer 0 ----
    ep_k<<<2048, 256>>>(ea, l0We);
    node_proj_k<<<2048, 256>>>(x0, l0Wl, l0bl, l0Wr, l0br);
    cudaMemsetAsync(pacc, 0, (size_t)NN * HID * sizeof(float));
    cudaMemsetAsync(pden, 0, (size_t)NN * 4 * sizeof(float));
    edge_pass_k<<<2048, 256>>>(ei, l0att);
    node_out_k<<<(NN * 16 + 255) / 256, 256>>>(l0bias);

    // ---- layer 1 ----
    ep_k<<<2048, 256>>>(ea, l1We);
    node_proj_k<<<2048, 256>>>((const float*)px, l1Wl, l1bl, l1Wr, l1br);
    cudaMemsetAsync(pacc, 0, (size_t)NN * HID * sizeof(float));
    cudaMemsetAsync(pden, 0, (size_t)NN * 4 * sizeof(float));
    edge_pass_k<<<2048, 256>>>(ei, l1att);
    node_out_pool_k<<<(NN * 16 + 255) / 256, 256>>>(l1bias, batch);

    // ---- MLP ----
    mlp_k<<<GG, OUTD>>>(W1, b1, W2, b2, out);
}

// round 7
// speedup vs baseline: 1.3855x; 1.0893x over previous
#include <cuda_runtime.h>
#include <cuda_fp16.h>

#define NN 100000
#define EE 1600000
#define E2 (EE + NN)
#define GG 64
#define HID 64
#define EDIM 16
#define OUTD 128

// ---------------- scratch (device globals; no allocation) ----------------
__device__ float d_cnt[NN];
__device__ float d_loop[NN * EDIM];
__device__ float d_xl[NN * HID];
__device__ float d_xr[NN * HID];
__device__ float d_acc[NN * HID];
__device__ float d_den[NN * 4];
__device__ float d_g[GG * HID];
__device__ float d_gc[GG];
__device__ __half2 d_ep[(size_t)E2 * 32];   // precomputed ea @ We, fp16 (218 MB)

__device__ __forceinline__ void red4(float* p, float a, float b, float c, float d) {
    asm volatile("red.global.add.v4.f32 [%0], {%1,%2,%3,%4};"
                 :: "l"(p), "f"(a), "f"(b), "f"(c), "f"(d) : "memory");
}
__device__ __forceinline__ void red2(float* p, float a, float b) {
    asm volatile("red.global.add.v2.f32 [%0], {%1,%2};"
                 :: "l"(p), "f"(a), "f"(b) : "memory");
}

// ---------------- self-loop mean edge attr ----------------
__global__ void loop_accum_k(const int* __restrict__ ei, const float* __restrict__ ea) {
    int e = blockIdx.x * blockDim.x + threadIdx.x;
    if (e >= EE) return;
    int dst = ei[EE + e];
    const float4* a4 = reinterpret_cast<const float4*>(ea + (size_t)e * EDIM);
    float* o = d_loop + (size_t)dst * EDIM;
#pragma unroll
    for (int i = 0; i < 4; i++) {
        float4 v = a4[i];
        red4(o + 4 * i, v.x, v.y, v.z, v.w);
    }
    atomicAdd(&d_cnt[dst], 1.0f);
}

__global__ void loop_norm_k() {
    int t = blockIdx.x * blockDim.x + threadIdx.x;
    if (t >= NN * EDIM) return;
    float c = d_cnt[t >> 4];
    d_loop[t] = d_loop[t] / fmaxf(c, 1.0f);
}

// ---------------- edge projection precompute: d_ep = ea @ We (fp16 out) ----------------
// Warp handles an edge pair; attrs of both edges = one coalesced LDG.32/lane.
// Lane l owns channels {2l, 2l+1}.
__global__ void ep_k(const float* __restrict__ ea, const float* __restrict__ We) {
    const unsigned F = 0xffffffffu;
    int lane = threadIdx.x & 31;
    float2 w[EDIM];
    const float2* We2 = reinterpret_cast<const float2*>(We);
#pragma unroll
    for (int k = 0; k < EDIM; k++) w[k] = We2[k * 32 + lane];

    int wid = (blockIdx.x * blockDim.x + threadIdx.x) >> 5;
    int nwarp = (gridDim.x * blockDim.x) >> 5;

    for (int i = wid; i < E2 / 2; i += nwarp) {
        int e0 = 2 * i;
        const float* ap = (e0 < EE) ? (ea + (size_t)e0 * EDIM)
                                    : (d_loop + (size_t)(e0 - EE) * EDIM);
        float av = ap[lane];   // lanes 0-15: edge e0, lanes 16-31: edge e0+1
        float ex0 = 0.0f, ey0 = 0.0f, ex1 = 0.0f, ey1 = 0.0f;
#pragma unroll
        for (int k = 0; k < EDIM; k++) {
            float a0 = __shfl_sync(F, av, k);
            float a1 = __shfl_sync(F, av, k + 16);
            ex0 += a0 * w[k].x;
            ey0 += a0 * w[k].y;
            ex1 += a1 * w[k].x;
            ey1 += a1 * w[k].y;
        }
        d_ep[(size_t)e0 * 32 + lane] = __floats2half2_rn(ex0, ey0);
        d_ep[(size_t)(e0 + 1) * 32 + lane] = __floats2half2_rn(ex1, ey1);
    }
}

// ---------------- node projections (layer 0: plain input) ----------------
__global__ void node_proj_k(const float* __restrict__ x,
                            const float* __restrict__ Wl, const float* __restrict__ bl,
                            const float* __restrict__ Wr, const float* __restrict__ br) {
    __shared__ float sWl[64 * 64];
    __shared__ float sWr[64 * 64];
    __shared__ float sx[16 * 64];
    for (int i = threadIdx.x; i < 64 * 16; i += blockDim.x) {
        reinterpret_cast<float4*>(sWl)[i] = reinterpret_cast<const float4*>(Wl)[i];
        reinterpret_cast<float4*>(sWr)[i] = reinterpret_cast<const float4*>(Wr)[i];
    }
    int c  = threadIdx.x & 63;
    int rl = threadIdx.x >> 6;
    float blc = bl[c], brc = br[c];
    for (int base = blockIdx.x * 16; base < NN; base += gridDim.x * 16) {
        __syncthreads();
        for (int i = threadIdx.x; i < 16 * 16; i += 256) {
            int r = base + (i >> 4);
            reinterpret_cast<float4*>(sx)[i] = (r < NN)
                ? reinterpret_cast<const float4*>(x)[(size_t)r * 16 + (i & 15)]
                : make_float4(0.f, 0.f, 0.f, 0.f);
        }
        __syncthreads();
        float s0 = blc, s1 = blc, s2 = blc, s3 = blc;
        float t0 = brc, t1 = brc, t2 = brc, t3 = brc;
        const float* xrow = sx + rl * 4 * 64;
#pragma unroll
        for (int k = 0; k < 64; k++) {
            float wl = sWl[k * 64 + c];
            float wr = sWr[k * 64 + c];
            float x0 = xrow[0 * 64 + k];
            float x1 = xrow[1 * 64 + k];
            float x2 = xrow[2 * 64 + k];
            float x3 = xrow[3 * 64 + k];
            s0 += x0 * wl; t0 += x0 * wr;
            s1 += x1 * wl; t1 += x1 * wr;
            s2 += x2 * wl; t2 += x2 * wr;
            s3 += x3 * wl; t3 += x3 * wr;
        }
        int r0 = base + rl * 4;
        if (r0 + 0 < NN) { d_xl[(size_t)(r0 + 0) * 64 + c] = s0; d_xr[(size_t)(r0 + 0) * 64 + c] = t0; }
        if (r0 + 1 < NN) { d_xl[(size_t)(r0 + 1) * 64 + c] = s1; d_xr[(size_t)(r0 + 1) * 64 + c] = t1; }
        if (r0 + 2 < NN) { d_xl[(size_t)(r0 + 2) * 64 + c] = s2; d_xr[(size_t)(r0 + 2) * 64 + c] = t2; }
        if (r0 + 3 < NN) { d_xl[(size_t)(r0 + 3) * 64 + c] = s3; d_xr[(size_t)(r0 + 3) * 64 + c] = t3; }
    }
}

// ---------------- node projection (layer 1): input computed inline from acc/den ----------------
// x[r][c] = relu(acc[r][c] / den[r][c>>4] + bias0[c])  -- fuses layer-0 finalize.
__global__ void node_proj_fused_k(const float* __restrict__ bias0,
                                  const float* __restrict__ Wl, const float* __restrict__ bl,
                                  const float* __restrict__ Wr, const float* __restrict__ br) {
    __shared__ float sWl[64 * 64];
    __shared__ float sWr[64 * 64];
    __shared__ float sx[16 * 64];
    for (int i = threadIdx.x; i < 64 * 16; i += blockDim.x) {
        reinterpret_cast<float4*>(sWl)[i] = reinterpret_cast<const float4*>(Wl)[i];
        reinterpret_cast<float4*>(sWr)[i] = reinterpret_cast<const float4*>(Wr)[i];
    }
    int c  = threadIdx.x & 63;
    int rl = threadIdx.x >> 6;
    float blc = bl[c], brc = br[c];
    for (int base = blockIdx.x * 16; base < NN; base += gridDim.x * 16) {
        __syncthreads();
        for (int i = threadIdx.x; i < 16 * 16; i += 256) {
            int r = base + (i >> 4);
            int part = i & 15;
            float4 v = make_float4(0.f, 0.f, 0.f, 0.f);
            if (r < NN) {
                float inv = 1.0f / d_den[r * 4 + (part >> 2)];
                float4 a = reinterpret_cast<const float4*>(d_acc)[(size_t)r * 16 + part];
                float4 b = reinterpret_cast<const float4*>(bias0)[part];
                v.x = fmaxf(a.x * inv + b.x, 0.0f);
                v.y = fmaxf(a.y * inv + b.y, 0.0f);
                v.z = fmaxf(a.z * inv + b.z, 0.0f);
                v.w = fmaxf(a.w * inv + b.w, 0.0f);
            }
            reinterpret_cast<float4*>(sx)[i] = v;
        }
        __syncthreads();
        float s0 = blc, s1 = blc, s2 = blc, s3 = blc;
        float t0 = brc, t1 = brc, t2 = brc, t3 = brc;
        const float* xrow = sx + rl * 4 * 64;
#pragma unroll
        for (int k = 0; k < 64; k++) {
            float wl = sWl[k * 64 + c];
            float wr = sWr[k * 64 + c];
            float x0 = xrow[0 * 64 + k];
            float x1 = xrow[1 * 64 + k];
            float x2 = xrow[2 * 64 + k];
            float x3 = xrow[3 * 64 + k];
            s0 += x0 * wl; t0 += x0 * wr;
            s1 += x1 * wl; t1 += x1 * wr;
            s2 += x2 * wl; t2 += x2 * wr;
            s3 += x3 * wl; t3 += x3 * wr;
        }
        int r0 = base + rl * 4;
        if (r0 + 0 < NN) { d_xl[(size_t)(r0 + 0) * 64 + c] = s0; d_xr[(size_t)(r0 + 0) * 64 + c] = t0; }
        if (r0 + 1 < NN) { d_xl[(size_t)(r0 + 1) * 64 + c] = s1; d_xr[(size_t)(r0 + 1) * 64 + c] = t1; }
        if (r0 + 2 < NN) { d_xl[(size_t)(r0 + 2) * 64 + c] = s2; d_xr[(size_t)(r0 + 2) * 64 + c] = t2; }
        if (r0 + 3 < NN) { d_xl[(size_t)(r0 + 3) * 64 + c] = s3; d_xr[(size_t)(r0 + 3) * 64 + c] = t3; }
    }
}

// ---------------- edge pass: gather + score + exp + atomic accumulate ----------------
// Warp handles edge pair (2i, 2i+1); lane l owns channels {2l, 2l+1}.
// ep read as half2 (one LDG.32/lane/edge). Pairs never straddle EE.
__global__ __launch_bounds__(256)
void edge_pass_k(const int* __restrict__ ei, const float* __restrict__ att) {
    const unsigned F = 0xffffffffu;
    int lane = threadIdx.x & 31;
    float2 at = reinterpret_cast<const float2*>(att)[lane];

    int wid = (blockIdx.x * blockDim.x + threadIdx.x) >> 5;
    int nwarp = (gridDim.x * blockDim.x) >> 5;
    const float2* xl2p = reinterpret_cast<const float2*>(d_xl);
    const float2* xr2p = reinterpret_cast<const float2*>(d_xr);

    for (int i = wid; i < E2 / 2; i += nwarp) {
        int e0 = 2 * i;
        int s0i, s1i, d0i, d1i;
        if (e0 < EE) {
            int2 sp = *reinterpret_cast<const int2*>(ei + e0);
            int2 dp = *reinterpret_cast<const int2*>(ei + EE + e0);
            s0i = sp.x; s1i = sp.y; d0i = dp.x; d1i = dp.y;
        } else {
            s0i = d0i = e0 - EE;
            s1i = d1i = e0 - EE + 1;
        }
        float2 ep0 = __half22float2(d_ep[(size_t)e0 * 32 + lane]);
        float2 ep1 = __half22float2(d_ep[(size_t)(e0 + 1) * 32 + lane]);
        float2 xl0 = xl2p[(size_t)s0i * 32 + lane];
        float2 xr0 = xr2p[(size_t)d0i * 32 + lane];
        float2 xl1 = xl2p[(size_t)s1i * 32 + lane];
        float2 xr1 = xr2p[(size_t)d1i * 32 + lane];

        float m00 = xl0.x + xr0.x + ep0.x;
        float m01 = xl0.y + xr0.y + ep0.y;
        float m10 = xl1.x + xr1.x + ep1.x;
        float m11 = xl1.y + xr1.y + ep1.y;
        m00 = (m00 > 0.0f) ? m00 : 0.2f * m00;
        m01 = (m01 > 0.0f) ? m01 : 0.2f * m01;
        m10 = (m10 > 0.0f) ? m10 : 0.2f * m10;
        m11 = (m11 > 0.0f) ? m11 : 0.2f * m11;
        float sc0 = m00 * at.x + m01 * at.y;
        float sc1 = m10 * at.x + m11 * at.y;
        sc0 += __shfl_xor_sync(F, sc0, 1);
        sc1 += __shfl_xor_sync(F, sc1, 1);
        sc0 += __shfl_xor_sync(F, sc0, 2);
        sc1 += __shfl_xor_sync(F, sc1, 2);
        sc0 += __shfl_xor_sync(F, sc0, 4);
        sc1 += __shfl_xor_sync(F, sc1, 4);
        float z0 = __expf(sc0);   // softmax without max-shift (scores O(1))
        float z1 = __expf(sc1);

        red2(d_acc + (size_t)d0i * 64 + 2 * lane, z0 * xl0.x, z0 * xl0.y);
        red2(d_acc + (size_t)d1i * 64 + 2 * lane, z1 * xl1.x, z1 * xl1.y);
        if ((lane & 7) == 0) {
            atomicAdd(&d_den[(size_t)d0i * 4 + (lane >> 3)], z0);
            atomicAdd(&d_den[(size_t)d1i * 4 + (lane >> 3)], z1);
        }
    }
}

// ---------------- finalize layer 1 fused with global mean pool ----------------
__global__ void node_out_pool_k(const float* __restrict__ bias, const int* __restrict__ batch) {
    int t = blockIdx.x * blockDim.x + threadIdx.x;
    if (t >= NN * 16) return;
    int node = t >> 4;
    int part = t & 15;
    float inv = 1.0f / d_den[node * 4 + (part >> 2)];
    float4 a = reinterpret_cast<const float4*>(d_acc)[t];
    float4 b = reinterpret_cast<const float4*>(bias)[part];
    float vx = fmaxf(a.x * inv + b.x, 0.0f);
    float vy = fmaxf(a.y * inv + b.y, 0.0f);
    float vz = fmaxf(a.z * inv + b.z, 0.0f);
    float vw = fmaxf(a.w * inv + b.w, 0.0f);
    int g = batch[node];
    red4(d_g + g * 64 + part * 4, vx, vy, vz, vw);
    if (part == 0) atomicAdd(&d_gc[g], 1.0f);
}

// ---------------- MLP head ----------------
__global__ void mlp_k(const float* __restrict__ W1, const float* __restrict__ b1,
                      const float* __restrict__ W2, const float* __restrict__ b2,
                      float* __restrict__ out) {
    __shared__ float gx[64];
    __shared__ float hh[128];
    int g = blockIdx.x;
    int t = threadIdx.x;
    if (t < 64) gx[t] = d_g[g * 64 + t] / fmaxf(d_gc[g], 1.0f);
    __syncthreads();
    float s = b1[t];
#pragma unroll
    for (int k = 0; k < 64; k++) s += gx[k] * W1[k * 128 + t];
    hh[t] = fmaxf(s, 0.0f);
    __syncthreads();
    float o = b2[t];
#pragma unroll
    for (int k = 0; k < 128; k++) o += hh[k] * W2[k * 128 + t];
    out[g * 128 + t] = o;
}

// ---------------- launch ----------------
extern "C" void kernel_launch(void* const* d_in, const int* in_sizes, int n_in,
                              void* d_out, int out_size) {
    const float* x0     = (const float*)d_in[0];
    const int*   ei     = (const int*)d_in[1];
    const float* ea     = (const float*)d_in[2];
    const int*   batch  = (const int*)d_in[3];
    const float* l0Wl   = (const float*)d_in[4];
    const float* l0bl   = (const float*)d_in[5];
    const float* l0Wr   = (const float*)d_in[6];
    const float* l0br   = (const float*)d_in[7];
    const float* l0We   = (const float*)d_in[8];
    const float* l0att  = (const float*)d_in[9];
    const float* l0bias = (const float*)d_in[10];
    const float* l1Wl   = (const float*)d_in[11];
    const float* l1bl   = (const float*)d_in[12];
    const float* l1Wr   = (const float*)d_in[13];
    const float* l1br   = (const float*)d_in[14];
    const float* l1We   = (const float*)d_in[15];
    const float* l1att  = (const float*)d_in[16];
    const float* l1bias = (const float*)d_in[17];
    const float* W1     = (const float*)d_in[18];
    const float* b1     = (const float*)d_in[19];
    const float* W2     = (const float*)d_in[20];
    const float* b2     = (const float*)d_in[21];
    float* out = (float*)d_out;

    void *pcnt, *ploop, *pacc, *pden, *pg, *pgc;
    cudaGetSymbolAddress(&pcnt, d_cnt);
    cudaGetSymbolAddress(&ploop, d_loop);
    cudaGetSymbolAddress(&pacc, d_acc);
    cudaGetSymbolAddress(&pden, d_den);
    cudaGetSymbolAddress(&pg, d_g);
    cudaGetSymbolAddress(&pgc, d_gc);

    cudaMemsetAsync(pcnt, 0, NN * sizeof(float));
    cudaMemsetAsync(ploop, 0, NN * EDIM * sizeof(float));
    cudaMemsetAsync(pg, 0, GG * HID * sizeof(float));
    cudaMemsetAsync(pgc, 0, GG * sizeof(float));

    loop_accum_k<<<(EE + 255) / 256, 256>>>(ei, ea);
    loop_norm_k<<<(NN * EDIM + 255) / 256, 256>>>();

    // ---- layer 0 ----
    ep_k<<<2048, 256>>>(ea, l0We);
    node_proj_k<<<2048, 256>>>(x0, l0Wl, l0bl, l0Wr, l0br);
    cudaMemsetAsync(pacc, 0, (size_t)NN * HID * sizeof(float));
    cudaMemsetAsync(pden, 0, (size_t)NN * 4 * sizeof(float));
    edge_pass_k<<<2048, 256>>>(ei, l0att);

    // ---- layer 1 (layer-0 finalize fused into projection) ----
    ep_k<<<2048, 256>>>(ea, l1We);
    node_proj_fused_k<<<2048, 256>>>(l0bias, l1Wl, l1bl, l1Wr, l1br);
    cudaMemsetAsync(pacc, 0, (size_t)NN * HID * sizeof(float));
    cudaMemsetAsync(pden, 0, (size_t)NN * 4 * sizeof(float));
    edge_pass_k<<<2048, 256>>>(ei, l1att);
    node_out_pool_k<<<(NN * 16 + 255) / 256, 256>>>(l1bias, batch);

    // ---- MLP ----
    mlp_k<<<GG, OUTD>>>(W1, b1, W2, b2, out);
}

// round 8
// speedup vs baseline: 1.4322x; 1.0337x over previous
#include <cuda_runtime.h>
#include <cuda_fp16.h>

#define NN 100000
#define EE 1600000
#define E2 (EE + NN)
#define GG 64
#define HID 64
#define EDIM 16
#define OUTD 128

// ---------------- scratch (device globals; no allocation) ----------------
__device__ float d_cnt[NN];
__device__ float d_loop[NN * EDIM];
__device__ __half d_xl[NN * HID];          // source transform, fp16
__device__ __half d_xr[NN * HID];          // target transform, fp16
__device__ float d_acc[NN * HID];
__device__ float d_den[NN * 4];
__device__ float d_g[GG * HID];
__device__ float d_gc[GG];
__device__ __half2 d_ep[(size_t)E2 * 32];  // precomputed ea @ We, fp16

__device__ __forceinline__ void red4(float* p, float a, float b, float c, float d) {
    asm volatile("red.global.add.v4.f32 [%0], {%1,%2,%3,%4};"
                 :: "l"(p), "f"(a), "f"(b), "f"(c), "f"(d) : "memory");
}
__device__ __forceinline__ void red2(float* p, float a, float b) {
    asm volatile("red.global.add.v2.f32 [%0], {%1,%2};"
                 :: "l"(p), "f"(a), "f"(b) : "memory");
}

// ---------------- self-loop mean edge attr ----------------
__global__ void loop_accum_k(const int* __restrict__ ei, const float* __restrict__ ea) {
    int e = blockIdx.x * blockDim.x + threadIdx.x;
    if (e >= EE) return;
    int dst = ei[EE + e];
    const float4* a4 = reinterpret_cast<const float4*>(ea + (size_t)e * EDIM);
    float* o = d_loop + (size_t)dst * EDIM;
#pragma unroll
    for (int i = 0; i < 4; i++) {
        float4 v = a4[i];
        red4(o + 4 * i, v.x, v.y, v.z, v.w);
    }
    atomicAdd(&d_cnt[dst], 1.0f);
}

__global__ void loop_norm_k() {
    int t = blockIdx.x * blockDim.x + threadIdx.x;
    if (t >= NN * EDIM) return;
    float c = d_cnt[t >> 4];
    d_loop[t] = d_loop[t] / fmaxf(c, 1.0f);
}

// ---------------- edge projection precompute: d_ep = ea @ We (fp16 out) ----------------
__global__ void ep_k(const float* __restrict__ ea, const float* __restrict__ We) {
    const unsigned F = 0xffffffffu;
    int lane = threadIdx.x & 31;
    float2 w[EDIM];
    const float2* We2 = reinterpret_cast<const float2*>(We);
#pragma unroll
    for (int k = 0; k < EDIM; k++) w[k] = We2[k * 32 + lane];

    int wid = (blockIdx.x * blockDim.x + threadIdx.x) >> 5;
    int nwarp = (gridDim.x * blockDim.x) >> 5;

    for (int i = wid; i < E2 / 2; i += nwarp) {
        int e0 = 2 * i;
        const float* ap = (e0 < EE) ? (ea + (size_t)e0 * EDIM)
                                    : (d_loop + (size_t)(e0 - EE) * EDIM);
        float av = ap[lane];   // lanes 0-15: edge e0, lanes 16-31: edge e0+1
        float ex0 = 0.0f, ey0 = 0.0f, ex1 = 0.0f, ey1 = 0.0f;
#pragma unroll
        for (int k = 0; k < EDIM; k++) {
            float a0 = __shfl_sync(F, av, k);
            float a1 = __shfl_sync(F, av, k + 16);
            ex0 += a0 * w[k].x;
            ey0 += a0 * w[k].y;
            ex1 += a1 * w[k].x;
            ey1 += a1 * w[k].y;
        }
        d_ep[(size_t)e0 * 32 + lane] = __floats2half2_rn(ex0, ey0);
        d_ep[(size_t)(e0 + 1) * 32 + lane] = __floats2half2_rn(ex1, ey1);
    }
}

// ---------------- node projections (layer 0: plain input), fp16 outputs ----------------
__global__ void node_proj_k(const float* __restrict__ x,
                            const float* __restrict__ Wl, const float* __restrict__ bl,
                            const float* __restrict__ Wr, const float* __restrict__ br) {
    __shared__ float sWl[64 * 64];
    __shared__ float sWr[64 * 64];
    __shared__ float sx[16 * 64];
    for (int i = threadIdx.x; i < 64 * 16; i += blockDim.x) {
        reinterpret_cast<float4*>(sWl)[i] = reinterpret_cast<const float4*>(Wl)[i];
        reinterpret_cast<float4*>(sWr)[i] = reinterpret_cast<const float4*>(Wr)[i];
    }
    int c  = threadIdx.x & 63;
    int rl = threadIdx.x >> 6;
    float blc = bl[c], brc = br[c];
    for (int base = blockIdx.x * 16; base < NN; base += gridDim.x * 16) {
        __syncthreads();
        for (int i = threadIdx.x; i < 16 * 16; i += 256) {
            int r = base + (i >> 4);
            reinterpret_cast<float4*>(sx)[i] = (r < NN)
                ? reinterpret_cast<const float4*>(x)[(size_t)r * 16 + (i & 15)]
                : make_float4(0.f, 0.f, 0.f, 0.f);
        }
        __syncthreads();
        float s0 = blc, s1 = blc, s2 = blc, s3 = blc;
        float t0 = brc, t1 = brc, t2 = brc, t3 = brc;
        const float* xrow = sx + rl * 4 * 64;
#pragma unroll
        for (int k = 0; k < 64; k++) {
            float wl = sWl[k * 64 + c];
            float wr = sWr[k * 64 + c];
            float x0 = xrow[0 * 64 + k];
            float x1 = xrow[1 * 64 + k];
            float x2 = xrow[2 * 64 + k];
            float x3 = xrow[3 * 64 + k];
            s0 += x0 * wl; t0 += x0 * wr;
            s1 += x1 * wl; t1 += x1 * wr;
            s2 += x2 * wl; t2 += x2 * wr;
            s3 += x3 * wl; t3 += x3 * wr;
        }
        int r0 = base + rl * 4;
        if (r0 + 0 < NN) { d_xl[(size_t)(r0 + 0) * 64 + c] = __float2half(s0); d_xr[(size_t)(r0 + 0) * 64 + c] = __float2half(t0); }
        if (r0 + 1 < NN) { d_xl[(size_t)(r0 + 1) * 64 + c] = __float2half(s1); d_xr[(size_t)(r0 + 1) * 64 + c] = __float2half(t1); }
        if (r0 + 2 < NN) { d_xl[(size_t)(r0 + 2) * 64 + c] = __float2half(s2); d_xr[(size_t)(r0 + 2) * 64 + c] = __float2half(t2); }
        if (r0 + 3 < NN) { d_xl[(size_t)(r0 + 3) * 64 + c] = __float2half(s3); d_xr[(size_t)(r0 + 3) * 64 + c] = __float2half(t3); }
    }
}

// ---------------- node projection (layer 1): fuses layer-0 finalize ----------------
__global__ void node_proj_fused_k(const float* __restrict__ bias0,
                                  const float* __restrict__ Wl, const float* __restrict__ bl,
                                  const float* __restrict__ Wr, const float* __restrict__ br) {
    __shared__ float sWl[64 * 64];
    __shared__ float sWr[64 * 64];
    __shared__ float sx[16 * 64];
    for (int i = threadIdx.x; i < 64 * 16; i += blockDim.x) {
        reinterpret_cast<float4*>(sWl)[i] = reinterpret_cast<const float4*>(Wl)[i];
        reinterpret_cast<float4*>(sWr)[i] = reinterpret_cast<const float4*>(Wr)[i];
    }
    int c  = threadIdx.x & 63;
    int rl = threadIdx.x >> 6;
    float blc = bl[c], brc = br[c];
    for (int base = blockIdx.x * 16; base < NN; base += gridDim.x * 16) {
        __syncthreads();
        for (int i = threadIdx.x; i < 16 * 16; i += 256) {
            int r = base + (i >> 4);
            int part = i & 15;
            float4 v = make_float4(0.f, 0.f, 0.f, 0.f);
            if (r < NN) {
                float inv = 1.0f / d_den[r * 4 + (part >> 2)];
                float4 a = reinterpret_cast<const float4*>(d_acc)[(size_t)r * 16 + part];
                float4 b = reinterpret_cast<const float4*>(bias0)[part];
                v.x = fmaxf(a.x * inv + b.x, 0.0f);
                v.y = fmaxf(a.y * inv + b.y, 0.0f);
                v.z = fmaxf(a.z * inv + b.z, 0.0f);
                v.w = fmaxf(a.w * inv + b.w, 0.0f);
            }
            reinterpret_cast<float4*>(sx)[i] = v;
        }
        __syncthreads();
        float s0 = blc, s1 = blc, s2 = blc, s3 = blc;
        float t0 = brc, t1 = brc, t2 = brc, t3 = brc;
        const float* xrow = sx + rl * 4 * 64;
#pragma unroll
        for (int k = 0; k < 64; k++) {
            float wl = sWl[k * 64 + c];
            float wr = sWr[k * 64 + c];
            float x0 = xrow[0 * 64 + k];
            float x1 = xrow[1 * 64 + k];
            float x2 = xrow[2 * 64 + k];
            float x3 = xrow[3 * 64 + k];
            s0 += x0 * wl; t0 += x0 * wr;
            s1 += x1 * wl; t1 += x1 * wr;
            s2 += x2 * wl; t2 += x2 * wr;
            s3 += x3 * wl; t3 += x3 * wr;
        }
        int r0 = base + rl * 4;
        if (r0 + 0 < NN) { d_xl[(size_t)(r0 + 0) * 64 + c] = __float2half(s0); d_xr[(size_t)(r0 + 0) * 64 + c] = __float2half(t0); }
        if (r0 + 1 < NN) { d_xl[(size_t)(r0 + 1) * 64 + c] = __float2half(s1); d_xr[(size_t)(r0 + 1) * 64 + c] = __float2half(t1); }
        if (r0 + 2 < NN) { d_xl[(size_t)(r0 + 2) * 64 + c] = __float2half(s2); d_xr[(size_t)(r0 + 2) * 64 + c] = __float2half(t2); }
        if (r0 + 3 < NN) { d_xl[(size_t)(r0 + 3) * 64 + c] = __float2half(s3); d_xr[(size_t)(r0 + 3) * 64 + c] = __float2half(t3); }
    }
}

// ---------------- edge pass: fp16 gathers + score + exp + atomic accumulate ----------------
// Warp handles edge pair (2i, 2i+1); lane l owns channels {2l, 2l+1}.
// Gathers are half2 (4B/lane, 64B/warp). Pairs never straddle EE.
__global__ __launch_bounds__(256)
void edge_pass_k(const int* __restrict__ ei, const float* __restrict__ att) {
    const unsigned F = 0xffffffffu;
    int lane = threadIdx.x & 31;
    float2 at = reinterpret_cast<const float2*>(att)[lane];

    int wid = (blockIdx.x * blockDim.x + threadIdx.x) >> 5;
    int nwarp = (gridDim.x * blockDim.x) >> 5;
    const __half2* xl2p = reinterpret_cast<const __half2*>(d_xl);
    const __half2* xr2p = reinterpret_cast<const __half2*>(d_xr);

    for (int i = wid; i < E2 / 2; i += nwarp) {
        int e0 = 2 * i;
        int s0i, s1i, d0i, d1i;
        if (e0 < EE) {
            int2 sp = *reinterpret_cast<const int2*>(ei + e0);
            int2 dp = *reinterpret_cast<const int2*>(ei + EE + e0);
            s0i = sp.x; s1i = sp.y; d0i = dp.x; d1i = dp.y;
        } else {
            s0i = d0i = e0 - EE;
            s1i = d1i = e0 - EE + 1;
        }
        float2 ep0 = __half22float2(d_ep[(size_t)e0 * 32 + lane]);
        float2 ep1 = __half22float2(d_ep[(size_t)(e0 + 1) * 32 + lane]);
        float2 xl0 = __half22float2(xl2p[(size_t)s0i * 32 + lane]);
        float2 xr0 = __half22float2(xr2p[(size_t)d0i * 32 + lane]);
        float2 xl1 = __half22float2(xl2p[(size_t)s1i * 32 + lane]);
        float2 xr1 = __half22float2(xr2p[(size_t)d1i * 32 + lane]);

        float m00 = xl0.x + xr0.x + ep0.x;
        float m01 = xl0.y + xr0.y + ep0.y;
        float m10 = xl1.x + xr1.x + ep1.x;
        float m11 = xl1.y + xr1.y + ep1.y;
        m00 = (m00 > 0.0f) ? m00 : 0.2f * m00;
        m01 = (m01 > 0.0f) ? m01 : 0.2f * m01;
        m10 = (m10 > 0.0f) ? m10 : 0.2f * m10;
        m11 = (m11 > 0.0f) ? m11 : 0.2f * m11;
        float sc0 = m00 * at.x + m01 * at.y;
        float sc1 = m10 * at.x + m11 * at.y;
        sc0 += __shfl_xor_sync(F, sc0, 1);
        sc1 += __shfl_xor_sync(F, sc1, 1);
        sc0 += __shfl_xor_sync(F, sc0, 2);
        sc1 += __shfl_xor_sync(F, sc1, 2);
        sc0 += __shfl_xor_sync(F, sc0, 4);
        sc1 += __shfl_xor_sync(F, sc1, 4);
        float z0 = __expf(sc0);   // softmax without max-shift (scores O(1))
        float z1 = __expf(sc1);

        red2(d_acc + (size_t)d0i * 64 + 2 * lane, z0 * xl0.x, z0 * xl0.y);
        red2(d_acc + (size_t)d1i * 64 + 2 * lane, z1 * xl1.x, z1 * xl1.y);
        if ((lane & 7) == 0) {
            atomicAdd(&d_den[(size_t)d0i * 4 + (lane >> 3)], z0);
            atomicAdd(&d_den[(size_t)d1i * 4 + (lane >> 3)], z1);
        }
    }
}

// ---------------- finalize layer 1 fused with global mean pool ----------------
__global__ void node_out_pool_k(const float* __restrict__ bias, const int* __restrict__ batch) {
    int t = blockIdx.x * blockDim.x + threadIdx.x;
    if (t >= NN * 16) return;
    int node = t >> 4;
    int part = t & 15;
    float inv = 1.0f / d_den[node * 4 + (part >> 2)];
    float4 a = reinterpret_cast<const float4*>(d_acc)[t];
    float4 b = reinterpret_cast<const float4*>(bias)[part];
    float vx = fmaxf(a.x * inv + b.x, 0.0f);
    float vy = fmaxf(a.y * inv + b.y, 0.0f);
    float vz = fmaxf(a.z * inv + b.z, 0.0f);
    float vw = fmaxf(a.w * inv + b.w, 0.0f);
    int g = batch[node];
    red4(d_g + g * 64 + part * 4, vx, vy, vz, vw);
    if (part == 0) atomicAdd(&d_gc[g], 1.0f);
}

// ---------------- MLP head ----------------
__global__ void mlp_k(const float* __restrict__ W1, const float* __restrict__ b1,
                      const float* __restrict__ W2, const float* __restrict__ b2,
                      float* __restrict__ out) {
    __shared__ float gx[64];
    __shared__ float hh[128];
    int g = blockIdx.x;
    int t = threadIdx.x;
    if (t < 64) gx[t] = d_g[g * 64 + t] / fmaxf(d_gc[g], 1.0f);
    __syncthreads();
    float s = b1[t];
#pragma unroll
    for (int k = 0; k < 64; k++) s += gx[k] * W1[k * 128 + t];
    hh[t] = fmaxf(s, 0.0f);
    __syncthreads();
    float o = b2[t];
#pragma unroll
    for (int k = 0; k < 128; k++) o += hh[k] * W2[k * 128 + t];
    out[g * 128 + t] = o;
}

// ---------------- launch ----------------
extern "C" void kernel_launch(void* const* d_in, const int* in_sizes, int n_in,
                              void* d_out, int out_size) {
    const float* x0     = (const float*)d_in[0];
    const int*   ei     = (const int*)d_in[1];
    const float* ea     = (const float*)d_in[2];
    const int*   batch  = (const int*)d_in[3];
    const float* l0Wl   = (const float*)d_in[4];
    const float* l0bl   = (const float*)d_in[5];
    const float* l0Wr   = (const float*)d_in[6];
    const float* l0br   = (const float*)d_in[7];
    const float* l0We   = (const float*)d_in[8];
    const float* l0att  = (const float*)d_in[9];
    const float* l0bias = (const float*)d_in[10];
    const float* l1Wl   = (const float*)d_in[11];
    const float* l1bl   = (const float*)d_in[12];
    const float* l1Wr   = (const float*)d_in[13];
    const float* l1br   = (const float*)d_in[14];
    const float* l1We   = (const float*)d_in[15];
    const float* l1att  = (const float*)d_in[16];
    const float* l1bias = (const float*)d_in[17];
    const float* W1     = (const float*)d_in[18];
    const float* b1     = (const float*)d_in[19];
    const float* W2     = (const float*)d_in[20];
    const float* b2     = (const float*)d_in[21];
    float* out = (float*)d_out;

    void *pcnt, *ploop, *pacc, *pden, *pg, *pgc;
    cudaGetSymbolAddress(&pcnt, d_cnt);
    cudaGetSymbolAddress(&ploop, d_loop);
    cudaGetSymbolAddress(&pacc, d_acc);
    cudaGetSymbolAddress(&pden, d_den);
    cudaGetSymbolAddress(&pg, d_g);
    cudaGetSymbolAddress(&pgc, d_gc);

    cudaMemsetAsync(pcnt, 0, NN * sizeof(float));
    cudaMemsetAsync(ploop, 0, NN * EDIM * sizeof(float));
    cudaMemsetAsync(pg, 0, GG * HID * sizeof(float));
    cudaMemsetAsync(pgc, 0, GG * sizeof(float));

    loop_accum_k<<<(EE + 255) / 256, 256>>>(ei, ea);
    loop_norm_k<<<(NN * EDIM + 255) / 256, 256>>>();

    // ---- layer 0 ----
    ep_k<<<2048, 256>>>(ea, l0We);
    node_proj_k<<<2048, 256>>>(x0, l0Wl, l0bl, l0Wr, l0br);
    cudaMemsetAsync(pacc, 0, (size_t)NN * HID * sizeof(float));
    cudaMemsetAsync(pden, 0, (size_t)NN * 4 * sizeof(float));
    edge_pass_k<<<2048, 256>>>(ei, l0att);

    // ---- layer 1 (layer-0 finalize fused into projection) ----
    ep_k<<<2048, 256>>>(ea, l1We);
    node_proj_fused_k<<<2048, 256>>>(l0bias, l1Wl, l1bl, l1Wr, l1br);
    cudaMemsetAsync(pacc, 0, (size_t)NN * HID * sizeof(float));
    cudaMemsetAsync(pden, 0, (size_t)NN * 4 * sizeof(float));
    edge_pass_k<<<2048, 256>>>(ei, l1att);
    node_out_pool_k<<<(NN * 16 + 255) / 256, 256>>>(l1bias, batch);

    // ---- MLP ----
    mlp_k<<<GG, OUTD>>>(W1, b1, W2, b2, out);
}